// round 14
// baseline (speedup 1.0000x reference)
#include <cuda_runtime.h>
#include <cuda_fp16.h>
#include <cstdint>

#define N_NODES 40000
#define N_EDGES 640000
#define D_FEAT  128
#define NB_SCAN 157          // ceil(N_NODES / 256)

// ---------------------------------------------------------------------------
// Static scratch (no cudaMalloc allowed). Zero-initialized at module load;
// the gather epilogue restores the zeros every run (graph-replay invariant).
// ---------------------------------------------------------------------------
__device__ int                g_count  [N_NODES];
__device__ unsigned long long g_pub    [NB_SCAN];   // (flag<<32) | block aggregate
__device__ int                g_offsets[N_NODES + 1];
__device__ int                g_cursor [N_NODES];
__device__ int2               g_edge   [N_EDGES];   // {col, float-bits of val}
__device__ uint2              g_xh     [N_NODES * 32]; // x in fp16, 32 uint2/row

// ---------------------------------------------------------------------------
// Block-wide inclusive scan (256 threads). smem must hold >= 32 ints.
// ---------------------------------------------------------------------------
__device__ __forceinline__ int block_incl_scan(int v, int* smem)
{
    const int lane = threadIdx.x & 31;
    const int wid  = threadIdx.x >> 5;
    #pragma unroll
    for (int o = 1; o < 32; o <<= 1) {
        int n = __shfl_up_sync(0xffffffffu, v, o);
        if (lane >= o) v += n;
    }
    if (lane == 31) smem[wid] = v;
    __syncthreads();
    if (wid == 0) {
        int w = (lane < 8) ? smem[lane] : 0;
        #pragma unroll
        for (int o = 1; o < 8; o <<= 1) {
            int n = __shfl_up_sync(0xffffffffu, w, o);
            if (lane >= o) w += n;
        }
        if (lane < 8) smem[lane] = w;
    }
    __syncthreads();
    if (wid > 0) v += smem[wid - 1];
    return v;
}

// ---------------------------------------------------------------------------
// K1: fused convert (fp32 x -> fp16 g_xh, 1.28M threads) + histogram of
// destination rows (first 640K threads). g_count arrives zeroed (epilogue
// of the previous run / static init).
// ---------------------------------------------------------------------------
__global__ void __launch_bounds__(256) convert_hist_kernel(
    const float4* __restrict__ x4,
    const int*    __restrict__ edge_rows)
{
    const int i = blockIdx.x * blockDim.x + threadIdx.x;   // 0 .. 1,279,999

    if (i < N_NODES * 32) {
        const float4 v = x4[i];
        const __half2 a = __floats2half2_rn(v.x, v.y);
        const __half2 b = __floats2half2_rn(v.z, v.w);
        uint2 o;
        o.x = *reinterpret_cast<const unsigned int*>(&a);
        o.y = *reinterpret_cast<const unsigned int*>(&b);
        g_xh[i] = o;
    }
    if (i < N_EDGES)
        atomicAdd(&g_count[edge_rows[i]], 1);
}

// ---------------------------------------------------------------------------
// K2: single-pass exclusive scan with decoupled lookback.
// Each block scans its 256 counts, publishes (1<<32 | aggregate) with one
// atomic 64-bit exchange, then each thread t < blockIdx.x polls block t's
// word (parallel lookback, no serial chain). Publish-before-poll + all 157
// blocks wave-1 resident -> no deadlock.
// ---------------------------------------------------------------------------
__global__ void __launch_bounds__(256) scan_kernel()
{
    __shared__ int smem[32];
    __shared__ int s_total;
    __shared__ int s_bp;

    const int t = threadIdx.x;
    const int b = blockIdx.x;
    const int i = b * 256 + t;

    int c = (i < N_NODES) ? g_count[i] : 0;
    int incl = block_incl_scan(c, smem);
    if (t == 255) s_total = incl;
    __syncthreads();

    if (t == 0)
        atomicExch(&g_pub[b], (1ULL << 32) | (unsigned long long)(unsigned)s_total);

    // parallel lookback: thread t grabs predecessor t's aggregate
    int contrib = 0;
    if (t < b) {
        unsigned long long v;
        do { v = atomicAdd(&g_pub[t], 0ULL); } while (!(v >> 32));
        contrib = (int)(unsigned)(v & 0xffffffffULL);
    }
    __syncthreads();                       // smem reuse below
    {
        const int lane = t & 31;
        const int wid  = t >> 5;
        int v = contrib;
        #pragma unroll
        for (int o = 16; o > 0; o >>= 1)
            v += __shfl_down_sync(0xffffffffu, v, o);
        if (lane == 0) smem[wid] = v;
        __syncthreads();
        if (t == 0) {
            int s = 0;
            #pragma unroll
            for (int w = 0; w < 8; w++) s += smem[w];
            s_bp = s;
        }
        __syncthreads();
    }

    const int off = s_bp + incl - c;
    if (i < N_NODES) {
        g_offsets[i] = off;
        g_cursor[i]  = off;
    }
    if (i == N_NODES - 1) g_offsets[N_NODES] = off + c;   // == N_EDGES
}

// ---------------------------------------------------------------------------
// K3: counting-sort permute (1 edge/thread, packed STG.64).
// ---------------------------------------------------------------------------
__global__ void __launch_bounds__(256) permute_kernel(
    const int*   __restrict__ edge_rows,
    const int*   __restrict__ edge_cols,
    const float* __restrict__ adj_vals)
{
    int i = blockIdx.x * blockDim.x + threadIdx.x;
    if (i >= N_EDGES) return;
    const int   r = edge_rows[i];
    const int   c = edge_cols[i];
    const float v = adj_vals[i];
    const int pos = atomicAdd(&g_cursor[r], 1);
    g_edge[pos] = make_int2(c, __float_as_int(v));
}

// ---------------------------------------------------------------------------
// K4: warp-per-node gather from fp16 x; fp32 accumulate; normalize + bias
// fused; out written once. Epilogue re-zeros g_count and g_pub so the next
// graph replay starts from a clean state (saves a zero kernel).
// ---------------------------------------------------------------------------
__global__ void __launch_bounds__(256) gather_kernel(
    const float4* __restrict__ bias4,
    float4*       __restrict__ out4)
{
    const int gtid = blockIdx.x * blockDim.x + threadIdx.x;
    const int warp = gtid >> 5;
    const int lane = threadIdx.x & 31;

    // cleanup for next run (independent of the gather work below)
    if (gtid < N_NODES / 4)
        reinterpret_cast<int4*>(g_count)[gtid] = make_int4(0, 0, 0, 0);
    if (gtid < NB_SCAN)
        g_pub[gtid] = 0ULL;

    if (warp >= N_NODES) return;

    const int start = g_offsets[warp];
    const int end   = g_offsets[warp + 1];

    float4 acc = make_float4(0.f, 0.f, 0.f, 0.f);
    float  deg = 0.f;

    for (int base = start; base < end; base += 32) {
        const int e = base + lane;
        int2 ev = make_int2(0, 0);            // col=0, val=0.0f for invalid lanes
        if (e < end) ev = g_edge[e];

        const int cnt  = min(32, end - base);
        const int trip = (cnt + 7) & ~7;      // round up to multiple of 8

        #pragma unroll 8
        for (int j = 0; j < trip; j++) {
            const int   cc = __shfl_sync(0xffffffffu, ev.x, j);
            const float vv = __int_as_float(__shfl_sync(0xffffffffu, ev.y, j));
            const uint2 h  = g_xh[(size_t)cc * 32 + lane];
            const float2 f0 = __half22float2(*reinterpret_cast<const __half2*>(&h.x));
            const float2 f1 = __half22float2(*reinterpret_cast<const __half2*>(&h.y));
            acc.x += vv * f0.x;
            acc.y += vv * f0.y;
            acc.z += vv * f1.x;
            acc.w += vv * f1.y;
            deg   += vv;
        }
    }

    const float inv = (deg == 0.f) ? 0.f : 1.f / deg;
    const float4 b  = bias4[lane];
    float4 o;
    o.x = acc.x * inv + b.x;
    o.y = acc.y * inv + b.y;
    o.z = acc.z * inv + b.z;
    o.w = acc.w * inv + b.w;
    out4[(size_t)warp * (D_FEAT / 4) + lane] = o;
}

// ---------------------------------------------------------------------------
extern "C" void kernel_launch(void* const* d_in, const int* in_sizes, int n_in,
                              void* d_out, int out_size)
{
    const float* x         = (const float*)d_in[0];
    const int*   edge_rows = (const int*)  d_in[1];
    const int*   edge_cols = (const int*)  d_in[2];
    const float* adj_vals  = (const float*)d_in[3];
    const float* bias      = (const float*)d_in[4];
    float*       out       = (float*)d_out;

    (void)in_sizes; (void)n_in; (void)out_size;

    convert_hist_kernel<<<(N_NODES * 32 + 255) / 256, 256>>>(
        (const float4*)x, edge_rows);
    scan_kernel<<<NB_SCAN, 256>>>();
    permute_kernel<<<(N_EDGES + 255) / 256, 256>>>(edge_rows, edge_cols, adj_vals);
    gather_kernel<<<(N_NODES * 32 + 255) / 256, 256>>>(
        (const float4*)bias, (float4*)out);
}

// round 15
// speedup vs baseline: 1.0755x; 1.0755x over previous
#include <cuda_runtime.h>
#include <cuda_fp16.h>
#include <cstdint>

#define N_NODES 40000
#define N_EDGES 640000
#define D_FEAT  128
#define NB_SCAN 157          // ceil(N_NODES / 256)

// ---------------------------------------------------------------------------
// Static scratch (no cudaMalloc allowed). Zero-initialized at module load;
// the gather epilogue restores the zeros every run (graph-replay invariant).
// ---------------------------------------------------------------------------
__device__ int                g_count  [N_NODES];
__device__ unsigned long long g_pub    [NB_SCAN];   // (flag<<32) | block aggregate
__device__ int                g_offsets[N_NODES + 1];
__device__ int                g_rank   [N_EDGES];   // rank of edge within its row
__device__ int2               g_edge   [N_EDGES];   // {col, float-bits of val}
__device__ uint2              g_xh     [N_NODES * 32]; // x in fp16, 32 uint2/row

// ---------------------------------------------------------------------------
// Block-wide inclusive scan (256 threads). smem must hold >= 32 ints.
// ---------------------------------------------------------------------------
__device__ __forceinline__ int block_incl_scan(int v, int* smem)
{
    const int lane = threadIdx.x & 31;
    const int wid  = threadIdx.x >> 5;
    #pragma unroll
    for (int o = 1; o < 32; o <<= 1) {
        int n = __shfl_up_sync(0xffffffffu, v, o);
        if (lane >= o) v += n;
    }
    if (lane == 31) smem[wid] = v;
    __syncthreads();
    if (wid == 0) {
        int w = (lane < 8) ? smem[lane] : 0;
        #pragma unroll
        for (int o = 1; o < 8; o <<= 1) {
            int n = __shfl_up_sync(0xffffffffu, w, o);
            if (lane >= o) w += n;
        }
        if (lane < 8) smem[lane] = w;
    }
    __syncthreads();
    if (wid > 0) v += smem[wid - 1];
    return v;
}

// ---------------------------------------------------------------------------
// K1: fused convert (fp32 x -> fp16 g_xh) + histogram WITH rank capture:
// the returning atomicAdd hands each edge its slot-within-row for free,
// removing the atomic from the permute pass entirely.
// ---------------------------------------------------------------------------
__global__ void __launch_bounds__(256) convert_hist_kernel(
    const float4* __restrict__ x4,
    const int*    __restrict__ edge_rows)
{
    const int i = blockIdx.x * blockDim.x + threadIdx.x;   // 0 .. 1,279,999

    if (i < N_NODES * 32) {
        const float4 v = x4[i];
        const __half2 a = __floats2half2_rn(v.x, v.y);
        const __half2 b = __floats2half2_rn(v.z, v.w);
        uint2 o;
        o.x = *reinterpret_cast<const unsigned int*>(&a);
        o.y = *reinterpret_cast<const unsigned int*>(&b);
        g_xh[i] = o;
    }
    if (i < N_EDGES)
        g_rank[i] = atomicAdd(&g_count[edge_rows[i]], 1);
}

// ---------------------------------------------------------------------------
// K2: single-pass exclusive scan with parallel decoupled lookback.
// ---------------------------------------------------------------------------
__global__ void __launch_bounds__(256) scan_kernel()
{
    __shared__ int smem[32];
    __shared__ int s_total;
    __shared__ int s_bp;

    const int t = threadIdx.x;
    const int b = blockIdx.x;
    const int i = b * 256 + t;

    int c = (i < N_NODES) ? g_count[i] : 0;
    int incl = block_incl_scan(c, smem);
    if (t == 255) s_total = incl;
    __syncthreads();

    if (t == 0)
        atomicExch(&g_pub[b], (1ULL << 32) | (unsigned long long)(unsigned)s_total);

    // parallel lookback: thread t grabs predecessor t's aggregate
    int contrib = 0;
    if (t < b) {
        unsigned long long v;
        do { v = atomicAdd(&g_pub[t], 0ULL); } while (!(v >> 32));
        contrib = (int)(unsigned)(v & 0xffffffffULL);
    }
    __syncthreads();                       // smem reuse below
    {
        const int lane = t & 31;
        const int wid  = t >> 5;
        int v = contrib;
        #pragma unroll
        for (int o = 16; o > 0; o >>= 1)
            v += __shfl_down_sync(0xffffffffu, v, o);
        if (lane == 0) smem[wid] = v;
        __syncthreads();
        if (t == 0) {
            int s = 0;
            #pragma unroll
            for (int w = 0; w < 8; w++) s += smem[w];
            s_bp = s;
        }
        __syncthreads();
    }

    const int off = s_bp + incl - c;
    if (i < N_NODES) g_offsets[i] = off;
    if (i == N_NODES - 1) g_offsets[N_NODES] = off + c;   // == N_EDGES
}

// ---------------------------------------------------------------------------
// K3: permutation WITHOUT atomics: pos = offsets[row] + precomputed rank.
// Pure coalesced loads + one scattered STG.64 per edge.
// ---------------------------------------------------------------------------
__global__ void __launch_bounds__(256) permute_kernel(
    const int*   __restrict__ edge_rows,
    const int*   __restrict__ edge_cols,
    const float* __restrict__ adj_vals)
{
    int i = blockIdx.x * blockDim.x + threadIdx.x;
    if (i >= N_EDGES) return;
    const int   r = edge_rows[i];
    const int   c = edge_cols[i];
    const float v = adj_vals[i];
    const int pos = g_offsets[r] + g_rank[i];
    g_edge[pos] = make_int2(c, __float_as_int(v));
}

// ---------------------------------------------------------------------------
// K4: warp-per-node gather, shuffle-free. Every lane needs the same edge, so
// each iteration does a broadcast LDG.64 of g_edge[e] (1 wavefront, 8 edges
// per 128B line -> L1-resident) instead of cooperative load + 2 SHFLs.
// Exact-bounds 4-unrolled loop: no trip padding, no predicates.
// Epilogue re-zeros g_count/g_pub for the next graph replay.
// ---------------------------------------------------------------------------
__device__ __forceinline__ void accum_edge(float4& acc, float& deg,
                                           const int2 ev, const int lane)
{
    const float vv = __int_as_float(ev.y);
    const uint2 h  = g_xh[(size_t)(unsigned)ev.x * 32 + lane];
    const float2 f0 = __half22float2(*reinterpret_cast<const __half2*>(&h.x));
    const float2 f1 = __half22float2(*reinterpret_cast<const __half2*>(&h.y));
    acc.x += vv * f0.x;
    acc.y += vv * f0.y;
    acc.z += vv * f1.x;
    acc.w += vv * f1.y;
    deg   += vv;
}

__global__ void __launch_bounds__(256) gather_kernel(
    const float4* __restrict__ bias4,
    float4*       __restrict__ out4)
{
    const int gtid = blockIdx.x * blockDim.x + threadIdx.x;
    const int warp = gtid >> 5;
    const int lane = threadIdx.x & 31;

    // cleanup for next run (independent of the gather work below)
    if (gtid < N_NODES / 4)
        reinterpret_cast<int4*>(g_count)[gtid] = make_int4(0, 0, 0, 0);
    if (gtid < NB_SCAN)
        g_pub[gtid] = 0ULL;

    if (warp >= N_NODES) return;

    const int start = g_offsets[warp];
    const int end   = g_offsets[warp + 1];

    float4 acc = make_float4(0.f, 0.f, 0.f, 0.f);
    float  deg = 0.f;

    int e = start;
    for (; e + 4 <= end; e += 4) {
        // four independent broadcast edge loads + four x-row loads in flight
        const int2 ev0 = g_edge[e + 0];
        const int2 ev1 = g_edge[e + 1];
        const int2 ev2 = g_edge[e + 2];
        const int2 ev3 = g_edge[e + 3];
        accum_edge(acc, deg, ev0, lane);
        accum_edge(acc, deg, ev1, lane);
        accum_edge(acc, deg, ev2, lane);
        accum_edge(acc, deg, ev3, lane);
    }
    for (; e < end; e++) {
        const int2 ev = g_edge[e];
        accum_edge(acc, deg, ev, lane);
    }

    const float inv = (deg == 0.f) ? 0.f : 1.f / deg;
    const float4 b  = bias4[lane];
    float4 o;
    o.x = acc.x * inv + b.x;
    o.y = acc.y * inv + b.y;
    o.z = acc.z * inv + b.z;
    o.w = acc.w * inv + b.w;
    out4[(size_t)warp * (D_FEAT / 4) + lane] = o;
}

// ---------------------------------------------------------------------------
extern "C" void kernel_launch(void* const* d_in, const int* in_sizes, int n_in,
                              void* d_out, int out_size)
{
    const float* x         = (const float*)d_in[0];
    const int*   edge_rows = (const int*)  d_in[1];
    const int*   edge_cols = (const int*)  d_in[2];
    const float* adj_vals  = (const float*)d_in[3];
    const float* bias      = (const float*)d_in[4];
    float*       out       = (float*)d_out;

    (void)in_sizes; (void)n_in; (void)out_size;

    convert_hist_kernel<<<(N_NODES * 32 + 255) / 256, 256>>>(
        (const float4*)x, edge_rows);
    scan_kernel<<<NB_SCAN, 256>>>();
    permute_kernel<<<(N_EDGES + 255) / 256, 256>>>(edge_rows, edge_cols, adj_vals);
    gather_kernel<<<(N_NODES * 32 + 255) / 256, 256>>>(
        (const float4*)bias, (float4*)out);
}

// round 16
// speedup vs baseline: 1.1276x; 1.0484x over previous
#include <cuda_runtime.h>
#include <cuda_fp16.h>
#include <cstdint>

#define N_NODES 40000
#define N_EDGES 640000
#define D_FEAT  128
#define NB_SCAN 157          // ceil(N_NODES / 256)

// ---------------------------------------------------------------------------
// Static scratch (no cudaMalloc allowed). Zero-initialized at module load;
// the gather epilogue restores the zeros every run (graph-replay invariant).
// ---------------------------------------------------------------------------
__device__ int                g_count  [N_NODES];
__device__ unsigned long long g_pub    [NB_SCAN];   // (flag<<32) | block aggregate
__device__ int                g_offsets[N_NODES + 1];
__device__ int                g_rank   [N_EDGES];   // rank of edge within its row
__device__ int2               g_edge   [N_EDGES];   // {col, float-bits of val}
__device__ uint2              g_xh     [N_NODES * 32]; // x in fp16, 32 uint2/row

// ---------------------------------------------------------------------------
// Block-wide inclusive scan (256 threads). smem must hold >= 32 ints.
// ---------------------------------------------------------------------------
__device__ __forceinline__ int block_incl_scan(int v, int* smem)
{
    const int lane = threadIdx.x & 31;
    const int wid  = threadIdx.x >> 5;
    #pragma unroll
    for (int o = 1; o < 32; o <<= 1) {
        int n = __shfl_up_sync(0xffffffffu, v, o);
        if (lane >= o) v += n;
    }
    if (lane == 31) smem[wid] = v;
    __syncthreads();
    if (wid == 0) {
        int w = (lane < 8) ? smem[lane] : 0;
        #pragma unroll
        for (int o = 1; o < 8; o <<= 1) {
            int n = __shfl_up_sync(0xffffffffu, w, o);
            if (lane >= o) w += n;
        }
        if (lane < 8) smem[lane] = w;
    }
    __syncthreads();
    if (wid > 0) v += smem[wid - 1];
    return v;
}

// ---------------------------------------------------------------------------
// K1: fused convert (fp32 x -> fp16 g_xh) + histogram WITH rank capture:
// the returning atomicAdd hands each edge its slot-within-row for free,
// removing the atomic from the permute pass entirely.
// ---------------------------------------------------------------------------
__global__ void __launch_bounds__(256) convert_hist_kernel(
    const float4* __restrict__ x4,
    const int*    __restrict__ edge_rows)
{
    const int i = blockIdx.x * blockDim.x + threadIdx.x;   // 0 .. 1,279,999

    if (i < N_NODES * 32) {
        const float4 v = x4[i];
        const __half2 a = __floats2half2_rn(v.x, v.y);
        const __half2 b = __floats2half2_rn(v.z, v.w);
        uint2 o;
        o.x = *reinterpret_cast<const unsigned int*>(&a);
        o.y = *reinterpret_cast<const unsigned int*>(&b);
        g_xh[i] = o;
    }
    if (i < N_EDGES)
        g_rank[i] = atomicAdd(&g_count[edge_rows[i]], 1);
}

// ---------------------------------------------------------------------------
// K2: single-pass exclusive scan with parallel decoupled lookback.
// ---------------------------------------------------------------------------
__global__ void __launch_bounds__(256) scan_kernel()
{
    __shared__ int smem[32];
    __shared__ int s_total;
    __shared__ int s_bp;

    const int t = threadIdx.x;
    const int b = blockIdx.x;
    const int i = b * 256 + t;

    int c = (i < N_NODES) ? g_count[i] : 0;
    int incl = block_incl_scan(c, smem);
    if (t == 255) s_total = incl;
    __syncthreads();

    if (t == 0)
        atomicExch(&g_pub[b], (1ULL << 32) | (unsigned long long)(unsigned)s_total);

    // parallel lookback: thread t grabs predecessor t's aggregate
    int contrib = 0;
    if (t < b) {
        unsigned long long v;
        do { v = atomicAdd(&g_pub[t], 0ULL); } while (!(v >> 32));
        contrib = (int)(unsigned)(v & 0xffffffffULL);
    }
    __syncthreads();                       // smem reuse below
    {
        const int lane = t & 31;
        const int wid  = t >> 5;
        int v = contrib;
        #pragma unroll
        for (int o = 16; o > 0; o >>= 1)
            v += __shfl_down_sync(0xffffffffu, v, o);
        if (lane == 0) smem[wid] = v;
        __syncthreads();
        if (t == 0) {
            int s = 0;
            #pragma unroll
            for (int w = 0; w < 8; w++) s += smem[w];
            s_bp = s;
        }
        __syncthreads();
    }

    const int off = s_bp + incl - c;
    if (i < N_NODES) g_offsets[i] = off;
    if (i == N_NODES - 1) g_offsets[N_NODES] = off + c;   // == N_EDGES
}

// ---------------------------------------------------------------------------
// K3: permutation WITHOUT atomics: pos = offsets[row] + precomputed rank.
// Pure coalesced loads + one scattered STG.64 per edge.
// ---------------------------------------------------------------------------
__global__ void __launch_bounds__(256) permute_kernel(
    const int*   __restrict__ edge_rows,
    const int*   __restrict__ edge_cols,
    const float* __restrict__ adj_vals)
{
    int i = blockIdx.x * blockDim.x + threadIdx.x;
    if (i >= N_EDGES) return;
    const int   r = edge_rows[i];
    const int   c = edge_cols[i];
    const float v = adj_vals[i];
    const int pos = g_offsets[r] + g_rank[i];
    g_edge[pos] = make_int2(c, __float_as_int(v));
}

// ---------------------------------------------------------------------------
// K4: warp-per-node gather, shuffle-free. Every lane needs the same edge, so
// each iteration does a broadcast LDG.64 of g_edge[e] (1 wavefront, 8 edges
// per 128B line -> L1-resident) instead of cooperative load + 2 SHFLs.
// Exact-bounds 4-unrolled loop: no trip padding, no predicates.
// Epilogue re-zeros g_count/g_pub for the next graph replay.
// ---------------------------------------------------------------------------
__device__ __forceinline__ void accum_edge(float4& acc, float& deg,
                                           const int2 ev, const int lane)
{
    const float vv = __int_as_float(ev.y);
    const uint2 h  = g_xh[(size_t)(unsigned)ev.x * 32 + lane];
    const float2 f0 = __half22float2(*reinterpret_cast<const __half2*>(&h.x));
    const float2 f1 = __half22float2(*reinterpret_cast<const __half2*>(&h.y));
    acc.x += vv * f0.x;
    acc.y += vv * f0.y;
    acc.z += vv * f1.x;
    acc.w += vv * f1.y;
    deg   += vv;
}

__global__ void __launch_bounds__(256) gather_kernel(
    const float4* __restrict__ bias4,
    float4*       __restrict__ out4)
{
    const int gtid = blockIdx.x * blockDim.x + threadIdx.x;
    const int warp = gtid >> 5;
    const int lane = threadIdx.x & 31;

    // cleanup for next run (independent of the gather work below)
    if (gtid < N_NODES / 4)
        reinterpret_cast<int4*>(g_count)[gtid] = make_int4(0, 0, 0, 0);
    if (gtid < NB_SCAN)
        g_pub[gtid] = 0ULL;

    if (warp >= N_NODES) return;

    const int start = g_offsets[warp];
    const int end   = g_offsets[warp + 1];

    float4 acc = make_float4(0.f, 0.f, 0.f, 0.f);
    float  deg = 0.f;

    int e = start;
    for (; e + 4 <= end; e += 4) {
        // four independent broadcast edge loads + four x-row loads in flight
        const int2 ev0 = g_edge[e + 0];
        const int2 ev1 = g_edge[e + 1];
        const int2 ev2 = g_edge[e + 2];
        const int2 ev3 = g_edge[e + 3];
        accum_edge(acc, deg, ev0, lane);
        accum_edge(acc, deg, ev1, lane);
        accum_edge(acc, deg, ev2, lane);
        accum_edge(acc, deg, ev3, lane);
    }
    for (; e < end; e++) {
        const int2 ev = g_edge[e];
        accum_edge(acc, deg, ev, lane);
    }

    const float inv = (deg == 0.f) ? 0.f : 1.f / deg;
    const float4 b  = bias4[lane];
    float4 o;
    o.x = acc.x * inv + b.x;
    o.y = acc.y * inv + b.y;
    o.z = acc.z * inv + b.z;
    o.w = acc.w * inv + b.w;
    out4[(size_t)warp * (D_FEAT / 4) + lane] = o;
}

// ---------------------------------------------------------------------------
extern "C" void kernel_launch(void* const* d_in, const int* in_sizes, int n_in,
                              void* d_out, int out_size)
{
    const float* x         = (const float*)d_in[0];
    const int*   edge_rows = (const int*)  d_in[1];
    const int*   edge_cols = (const int*)  d_in[2];
    const float* adj_vals  = (const float*)d_in[3];
    const float* bias      = (const float*)d_in[4];
    float*       out       = (float*)d_out;

    (void)in_sizes; (void)n_in; (void)out_size;

    convert_hist_kernel<<<(N_NODES * 32 + 255) / 256, 256>>>(
        (const float4*)x, edge_rows);
    scan_kernel<<<NB_SCAN, 256>>>();
    permute_kernel<<<(N_EDGES + 255) / 256, 256>>>(edge_rows, edge_cols, adj_vals);
    gather_kernel<<<(N_NODES * 32 + 255) / 256, 256>>>(
        (const float4*)bias, (float4*)out);
}